// round 4
// baseline (speedup 1.0000x reference)
#include <cuda_runtime.h>
#include <math.h>

#define BSZ      131072
#define ROWS     64
#define NTHREADS 512
#define KT       64
#define SA       260   // stride for 256-wide activation buffers (mult of 4)
#define S3A      68    // stride for 64-wide a3/w3 buffer (mult of 4)
#define SW       258   // stride for staged weight tile rows (even; mod 32 = 2)

struct SmemLayout {
    float X[ROWS][4];
    float A1[ROWS * SA];
    float A2[ROWS * SA];
    float A3[ROWS * S3A];
    float WT[KT * SW];
    float Vpart[8][2][8];
    float Upart[8][2][8];
    float Gpart[8][2][8][4];
    float Grad[ROWS * 4];
    float Vv[ROWS];
    float Uu[ROWS];
};

typedef unsigned long long ull;

__device__ __forceinline__ ull dup2(float a) {
    ull r; unsigned int u = __float_as_uint(a);
    asm("mov.b64 %0, {%1, %1};" : "=l"(r) : "r"(u));
    return r;
}
__device__ __forceinline__ void unpack2(ull v, float& lo, float& hi) {
    unsigned int l, h;
    asm("mov.b64 {%0, %1}, %2;" : "=r"(l), "=r"(h) : "l"(v));
    lo = __uint_as_float(l); hi = __uint_as_float(h);
}
__device__ __forceinline__ void ffma2(ull& d, ull a, ull b) {
    asm("fma.rn.f32x2 %0, %1, %2, %0;" : "+l"(d) : "l"(a), "l"(b));
}

// ---------- N=256 GEMM, packed output-column pairs ----------
// Thread (rgrp = tid>>6, cgrp = tid&63) owns rows rgrp*8..+7 and column pairs
// n0 = 2*(cgrp + 64*m), m in {0,1}.  A warp shares one rgrp -> act loads are
// warp broadcasts; weight loads are lane-consecutive LDS.64.
// TRANSW=false: W is [256][ldw], stage W[n][k]   (forward: z = a @ W^T)
// TRANSW=true : W is [K][ldw],   stage W[k][n]   (backward: t = v @ W)
template <int K, bool TRANSW>
__device__ __forceinline__ void gemm256(const float* __restrict__ W, int ldw,
                                        const float* __restrict__ sA, int lda,
                                        float* __restrict__ sWT,
                                        ull (&acc)[8][2], int tid) {
    const int rgrp = tid >> 6;
    const int cgrp = tid & 63;
    for (int k0 = 0; k0 < K; k0 += KT) {
        __syncthreads();
        if (TRANSW) {
            #pragma unroll
            for (int idx = tid; idx < 256 * KT / 2; idx += NTHREADS) {
                int n2 = idx % 128;          // float2 index within row
                int kk = idx / 128;
                *reinterpret_cast<float2*>(&sWT[kk * SW + n2 * 2]) =
                    *reinterpret_cast<const float2*>(&W[(k0 + kk) * ldw + n2 * 2]);
            }
        } else {
            #pragma unroll
            for (int idx = tid; idx < 256 * KT; idx += NTHREADS) {
                int kk = idx % KT;           // consecutive tid -> consecutive kk
                int n  = idx / KT;
                sWT[kk * SW + n] = W[n * ldw + k0 + kk];
            }
        }
        __syncthreads();
        #pragma unroll 2
        for (int kq = 0; kq < KT / 4; kq++) {
            float4 av[8];
            #pragma unroll
            for (int i = 0; i < 8; i++)
                av[i] = *reinterpret_cast<const float4*>(
                            &sA[(rgrp * 8 + i) * lda + k0 + kq * 4]);
            #pragma unroll
            for (int q = 0; q < 4; q++) {
                ull ad[8];
                #pragma unroll
                for (int i = 0; i < 8; i++) {
                    float a = (q == 0) ? av[i].x : (q == 1) ? av[i].y
                            : (q == 2) ? av[i].z : av[i].w;
                    ad[i] = dup2(a);
                }
                const float* wrow = sWT + (kq * 4 + q) * SW;
                #pragma unroll
                for (int m = 0; m < 2; m++) {
                    ull w2 = *reinterpret_cast<const ull*>(
                                 &wrow[2 * (cgrp + 64 * m)]);
                    #pragma unroll
                    for (int i = 0; i < 8; i++)
                        ffma2(acc[i][m], ad[i], w2);
                }
            }
        }
    }
}

// ---------- N=64 GEMM (layer 3 forward), one scalar column per thread ----------
__device__ __forceinline__ void gemm64(const float* __restrict__ W, int ldw,
                                       const float* __restrict__ sA, int lda,
                                       float* __restrict__ sWT,
                                       float (&acc)[8], int tid) {
    const int rgrp = tid >> 6;
    const int cgrp = tid & 63;
    for (int k0 = 0; k0 < 256; k0 += KT) {
        __syncthreads();
        #pragma unroll
        for (int idx = tid; idx < 64 * KT; idx += NTHREADS) {
            int kk = idx % KT;
            int n  = idx / KT;
            sWT[kk * SW + n] = W[n * ldw + k0 + kk];
        }
        __syncthreads();
        #pragma unroll 2
        for (int kq = 0; kq < KT / 4; kq++) {
            float4 av[8];
            #pragma unroll
            for (int i = 0; i < 8; i++)
                av[i] = *reinterpret_cast<const float4*>(
                            &sA[(rgrp * 8 + i) * lda + k0 + kq * 4]);
            #pragma unroll
            for (int q = 0; q < 4; q++) {
                float w = sWT[(kq * 4 + q) * SW + cgrp];
                #pragma unroll
                for (int i = 0; i < 8; i++) {
                    float a = (q == 0) ? av[i].x : (q == 1) ? av[i].y
                            : (q == 2) ? av[i].z : av[i].w;
                    acc[i] = fmaf(a, w, acc[i]);
                }
            }
        }
    }
}

__device__ __forceinline__ float redux32(float v) {
    v += __shfl_xor_sync(0xffffffffu, v, 16);
    v += __shfl_xor_sync(0xffffffffu, v, 8);
    v += __shfl_xor_sync(0xffffffffu, v, 4);
    v += __shfl_xor_sync(0xffffffffu, v, 2);
    v += __shfl_xor_sync(0xffffffffu, v, 1);
    return v;
}

__global__ void __launch_bounds__(NTHREADS, 1)
clf_kernel(const float* __restrict__ x,
           const float* __restrict__ Vw1, const float* __restrict__ Vb1,
           const float* __restrict__ Vw2, const float* __restrict__ Vb2,
           const float* __restrict__ Vw3, const float* __restrict__ Vb3,
           const float* __restrict__ Uw1, const float* __restrict__ Ub1,
           const float* __restrict__ Uw2, const float* __restrict__ Ub2,
           const float* __restrict__ Uw3, const float* __restrict__ Ub3,
           float* __restrict__ out) {
    extern __shared__ char smem_raw[];
    SmemLayout& S = *reinterpret_cast<SmemLayout*>(smem_raw);
    const int tid  = threadIdx.x;
    const int rgrp = tid >> 6;
    const int cgrp = tid & 63;
    const int wh   = (tid >> 5) & 1;   // warp half within the 64-thread rgrp
    const int lane = tid & 31;
    const int base = blockIdx.x * ROWS;

    // ---- load x tile (64 x 4) ----
    if (tid < 256) {
        int b = tid >> 2, j = tid & 3;
        S.X[b][j] = x[(base + b) * 4 + j];
    }
    __syncthreads();

    // ---- a1 = tanh(x @ Vw1^T + Vb1); thread pair (unit, half) ----
    {
        int unit = tid >> 1, h = tid & 1;
        float4 w = *reinterpret_cast<const float4*>(&Vw1[unit * 4]);
        float bb = Vb1[unit];
        #pragma unroll 4
        for (int b = h * 32; b < h * 32 + 32; b++) {
            float z = fmaf(S.X[b][0], w.x, bb);
            z = fmaf(S.X[b][1], w.y, z);
            z = fmaf(S.X[b][2], w.z, z);
            z = fmaf(S.X[b][3], w.w, z);
            S.A1[b * SA + unit] = tanhf(z);
        }
    }

    // ---- a2 = tanh(a1 @ Vw2^T + Vb2) ----
    {
        ull acc[8][2];
        #pragma unroll
        for (int i = 0; i < 8; i++) { acc[i][0] = 0ull; acc[i][1] = 0ull; }
        gemm256<256, false>(Vw2, 256, S.A1, SA, S.WT, acc, tid);
        #pragma unroll
        for (int m = 0; m < 2; m++) {
            int n0 = 2 * (cgrp + 64 * m);
            float2 bb = *reinterpret_cast<const float2*>(&Vb2[n0]);
            #pragma unroll
            for (int i = 0; i < 8; i++) {
                float lo, hi; unpack2(acc[i][m], lo, hi);
                float2 r;
                r.x = tanhf(lo + bb.x);
                r.y = tanhf(hi + bb.y);
                *reinterpret_cast<float2*>(&S.A2[(rgrp * 8 + i) * SA + n0]) = r;
            }
        }
    }

    // ---- a3 = tanh(a2 @ Vw3^T + Vb3); V = 0.5*sum a3^2; A3 = a3*(1-a3^2) ----
    {
        float acc[8];
        #pragma unroll
        for (int i = 0; i < 8; i++) acc[i] = 0.f;
        gemm64(Vw3, 256, S.A2, SA, S.WT, acc, tid);
        float bb = Vb3[cgrp];
        float pV[8];
        #pragma unroll
        for (int i = 0; i < 8; i++) {
            float a3 = tanhf(acc[i] + bb);
            pV[i] = a3 * a3;
            S.A3[(rgrp * 8 + i) * S3A + cgrp] = a3 * (1.f - a3 * a3);
        }
        #pragma unroll
        for (int i = 0; i < 8; i++) {
            float v = redux32(pV[i]);
            if (lane == 0) S.Vpart[rgrp][wh][i] = v;
        }
    }

    // ---- t2' = (w3 @ Vw3) * (1 - a2^2), written in place into A2 ----
    {
        ull acc[8][2];
        #pragma unroll
        for (int i = 0; i < 8; i++) { acc[i][0] = 0ull; acc[i][1] = 0ull; }
        gemm256<64, true>(Vw3, 256, S.A3, S3A, S.WT, acc, tid);
        #pragma unroll
        for (int m = 0; m < 2; m++) {
            int n0 = 2 * (cgrp + 64 * m);
            #pragma unroll
            for (int i = 0; i < 8; i++) {
                int off = (rgrp * 8 + i) * SA + n0;
                float2 a2v = *reinterpret_cast<const float2*>(&S.A2[off]);
                float lo, hi; unpack2(acc[i][m], lo, hi);
                float2 r;
                r.x = lo * (1.f - a2v.x * a2v.x);
                r.y = hi * (1.f - a2v.y * a2v.y);
                *reinterpret_cast<float2*>(&S.A2[off]) = r;
            }
        }
    }

    // ---- t1' = (t2' @ Vw2) * (1 - a1^2);  grad_V = t1' @ Vw1 ----
    {
        ull acc[8][2];
        #pragma unroll
        for (int i = 0; i < 8; i++) { acc[i][0] = 0ull; acc[i][1] = 0ull; }
        gemm256<256, true>(Vw2, 256, S.A2, SA, S.WT, acc, tid);
        float gp[8][4];
        #pragma unroll
        for (int i = 0; i < 8; i++)
            #pragma unroll
            for (int j = 0; j < 4; j++) gp[i][j] = 0.f;
        #pragma unroll
        for (int m = 0; m < 2; m++) {
            int n0 = 2 * (cgrp + 64 * m);
            float4 wa = *reinterpret_cast<const float4*>(&Vw1[n0 * 4]);
            float4 wb = *reinterpret_cast<const float4*>(&Vw1[(n0 + 1) * 4]);
            #pragma unroll
            for (int i = 0; i < 8; i++) {
                float2 a1v = *reinterpret_cast<const float2*>(
                                 &S.A1[(rgrp * 8 + i) * SA + n0]);
                float lo, hi; unpack2(acc[i][m], lo, hi);
                float t1lo = lo * (1.f - a1v.x * a1v.x);
                float t1hi = hi * (1.f - a1v.y * a1v.y);
                gp[i][0] = fmaf(t1lo, wa.x, fmaf(t1hi, wb.x, gp[i][0]));
                gp[i][1] = fmaf(t1lo, wa.y, fmaf(t1hi, wb.y, gp[i][1]));
                gp[i][2] = fmaf(t1lo, wa.z, fmaf(t1hi, wb.z, gp[i][2]));
                gp[i][3] = fmaf(t1lo, wa.w, fmaf(t1hi, wb.w, gp[i][3]));
            }
        }
        #pragma unroll
        for (int i = 0; i < 8; i++)
            #pragma unroll
            for (int j = 0; j < 4; j++) {
                float v = redux32(gp[i][j]);
                if (lane == 0) S.Gpart[rgrp][wh][i][j] = v;
            }
    }
    __syncthreads();  // A1/Gpart/Vpart settled

    // combine cross-warp partials
    if (tid < 64) {
        int b = tid;
        S.Vv[b] = 0.5f * (S.Vpart[b >> 3][0][b & 7] + S.Vpart[b >> 3][1][b & 7]);
    } else if (tid >= 128 && tid < 384) {
        int t = tid - 128;
        int b = t >> 2, j = t & 3;
        S.Grad[b * 4 + j] =
            S.Gpart[b >> 3][0][b & 7][j] + S.Gpart[b >> 3][1][b & 7][j];
    }

    // ---- u1 = tanh(x @ Uw1^T + Ub1), overwrite A1 ----
    {
        int unit = tid >> 1, h = tid & 1;
        float4 w = *reinterpret_cast<const float4*>(&Uw1[unit * 4]);
        float bb = Ub1[unit];
        #pragma unroll 4
        for (int b = h * 32; b < h * 32 + 32; b++) {
            float z = fmaf(S.X[b][0], w.x, bb);
            z = fmaf(S.X[b][1], w.y, z);
            z = fmaf(S.X[b][2], w.z, z);
            z = fmaf(S.X[b][3], w.w, z);
            S.A1[b * SA + unit] = tanhf(z);
        }
    }

    // ---- u2 = tanh(u1 @ Uw2^T + Ub2); fold dot with Uw3 ----
    {
        ull acc[8][2];
        #pragma unroll
        for (int i = 0; i < 8; i++) { acc[i][0] = 0ull; acc[i][1] = 0ull; }
        gemm256<256, false>(Uw2, 256, S.A1, SA, S.WT, acc, tid);
        float pu[8];
        #pragma unroll
        for (int i = 0; i < 8; i++) pu[i] = 0.f;
        #pragma unroll
        for (int m = 0; m < 2; m++) {
            int n0 = 2 * (cgrp + 64 * m);
            float2 uw = *reinterpret_cast<const float2*>(&Uw3[n0]);
            float2 bb = *reinterpret_cast<const float2*>(&Ub2[n0]);
            #pragma unroll
            for (int i = 0; i < 8; i++) {
                float lo, hi; unpack2(acc[i][m], lo, hi);
                pu[i] = fmaf(tanhf(lo + bb.x), uw.x, pu[i]);
                pu[i] = fmaf(tanhf(hi + bb.y), uw.y, pu[i]);
            }
        }
        #pragma unroll
        for (int i = 0; i < 8; i++) {
            float v = redux32(pu[i]);
            if (lane == 0) S.Upart[rgrp][wh][i] = v;
        }
    }
    __syncthreads();

    // ---- per-row epilogue: dynamics + Vdot + writes ----
    if (tid < ROWS) {
        int b = tid;
        float uu = S.Upart[b >> 3][0][b & 7] + S.Upart[b >> 3][1][b & 7];
        float u = 20.f * tanhf(uu + Ub3[0]);
        float th = S.X[b][1], v = S.X[b][2], om = S.X[b][3];
        float s, c;
        sincosf(th, &s, &c);
        float den1 = c - 24.7f;
        float den2 = c * c - 24.7f;
        float f2 = (c * (9.8f * s + 11.5f * v) + 68.4f * v - 1.2f * om * om * s) / den1;
        float f3 = (-58.8f * v * c - 243.5f * v - s * (208.3f + om * om * c)) / den2;
        float g2 = (-1.8f * c - 10.9f) / den1;
        float g3 = (9.3f * c + 38.6f) / den2;
        float gv0 = S.Grad[b * 4 + 0], gv1 = S.Grad[b * 4 + 1];
        float gv2 = S.Grad[b * 4 + 2], gv3 = S.Grad[b * 4 + 3];
        float Lf = gv0 * v + gv1 * om + gv2 * f2 + gv3 * f3;
        float Lg = gv2 * g2 + gv3 * g3;
        int row = base + b;
        out[row]           = u;            // u  [BS,1]
        out[BSZ + row]     = S.Vv[b];      // V  [BS]
        out[2 * BSZ + row] = Lf + Lg * u;  // Vdot [BS,1,1]
    }
}

extern "C" void kernel_launch(void* const* d_in, const int* in_sizes, int n_in,
                              void* d_out, int out_size) {
    const float* x   = (const float*)d_in[0];
    const float* Vw1 = (const float*)d_in[1];
    const float* Vb1 = (const float*)d_in[2];
    const float* Vw2 = (const float*)d_in[3];
    const float* Vb2 = (const float*)d_in[4];
    const float* Vw3 = (const float*)d_in[5];
    const float* Vb3 = (const float*)d_in[6];
    const float* Uw1 = (const float*)d_in[7];
    const float* Ub1 = (const float*)d_in[8];
    const float* Uw2 = (const float*)d_in[9];
    const float* Ub2 = (const float*)d_in[10];
    const float* Uw3 = (const float*)d_in[11];
    const float* Ub3 = (const float*)d_in[12];
    float* out = (float*)d_out;

    cudaFuncSetAttribute(clf_kernel, cudaFuncAttributeMaxDynamicSharedMemorySize,
                         (int)sizeof(SmemLayout));
    clf_kernel<<<BSZ / ROWS, NTHREADS, sizeof(SmemLayout)>>>(
        x, Vw1, Vb1, Vw2, Vb2, Vw3, Vb3, Uw1, Ub1, Uw2, Ub2, Uw3, Ub3, out);
}

// round 5
// speedup vs baseline: 1.0000x; 1.0000x over previous
#include <cuda_runtime.h>
#include <math.h>

#define BSZ      131072
#define ROWS     64
#define NTHREADS 512
#define KT       64
#define SA       260   // stride for 256-wide activation buffers (mult of 4)
#define S3A      68    // stride for 64-wide a3/w3 buffer (mult of 4)
#define SW       258   // stride for staged weight tile rows (even; mod 32 = 2)

struct SmemLayout {
    float X[ROWS][4];
    float A1[ROWS * SA];
    float A2[ROWS * SA];
    float A3[ROWS * S3A];
    float WT[KT * SW];
    float Vpart[8][2][8];
    float Upart[8][2][8];
    float Gpart[8][2][8][4];
    float Grad[ROWS * 4];
    float Vv[ROWS];
    float Uu[ROWS];
};

typedef unsigned long long ull;

__device__ __forceinline__ ull dup2(float a) {
    ull r; unsigned int u = __float_as_uint(a);
    asm("mov.b64 %0, {%1, %1};" : "=l"(r) : "r"(u));
    return r;
}
__device__ __forceinline__ void unpack2(ull v, float& lo, float& hi) {
    unsigned int l, h;
    asm("mov.b64 {%0, %1}, %2;" : "=r"(l), "=r"(h) : "l"(v));
    lo = __uint_as_float(l); hi = __uint_as_float(h);
}
__device__ __forceinline__ void ffma2(ull& d, ull a, ull b) {
    asm("fma.rn.f32x2 %0, %1, %2, %0;" : "+l"(d) : "l"(a), "l"(b));
}

// ---------- N=256 GEMM, packed output-column pairs ----------
// Thread (rgrp = tid>>6, cgrp = tid&63) owns rows rgrp*8..+7 and column pairs
// n0 = 2*(cgrp + 64*m), m in {0,1}.  A warp shares one rgrp -> act loads are
// warp broadcasts; weight loads are lane-consecutive LDS.64.
// TRANSW=false: W is [256][ldw], stage W[n][k]   (forward: z = a @ W^T)
// TRANSW=true : W is [K][ldw],   stage W[k][n]   (backward: t = v @ W)
template <int K, bool TRANSW>
__device__ __forceinline__ void gemm256(const float* __restrict__ W, int ldw,
                                        const float* __restrict__ sA, int lda,
                                        float* __restrict__ sWT,
                                        ull (&acc)[8][2], int tid) {
    const int rgrp = tid >> 6;
    const int cgrp = tid & 63;
    for (int k0 = 0; k0 < K; k0 += KT) {
        __syncthreads();
        if (TRANSW) {
            #pragma unroll
            for (int idx = tid; idx < 256 * KT / 2; idx += NTHREADS) {
                int n2 = idx % 128;          // float2 index within row
                int kk = idx / 128;
                *reinterpret_cast<float2*>(&sWT[kk * SW + n2 * 2]) =
                    *reinterpret_cast<const float2*>(&W[(k0 + kk) * ldw + n2 * 2]);
            }
        } else {
            #pragma unroll
            for (int idx = tid; idx < 256 * KT; idx += NTHREADS) {
                int kk = idx % KT;           // consecutive tid -> consecutive kk
                int n  = idx / KT;
                sWT[kk * SW + n] = W[n * ldw + k0 + kk];
            }
        }
        __syncthreads();
        #pragma unroll 2
        for (int kq = 0; kq < KT / 4; kq++) {
            float4 av[8];
            #pragma unroll
            for (int i = 0; i < 8; i++)
                av[i] = *reinterpret_cast<const float4*>(
                            &sA[(rgrp * 8 + i) * lda + k0 + kq * 4]);
            #pragma unroll
            for (int q = 0; q < 4; q++) {
                ull ad[8];
                #pragma unroll
                for (int i = 0; i < 8; i++) {
                    float a = (q == 0) ? av[i].x : (q == 1) ? av[i].y
                            : (q == 2) ? av[i].z : av[i].w;
                    ad[i] = dup2(a);
                }
                const float* wrow = sWT + (kq * 4 + q) * SW;
                #pragma unroll
                for (int m = 0; m < 2; m++) {
                    ull w2 = *reinterpret_cast<const ull*>(
                                 &wrow[2 * (cgrp + 64 * m)]);
                    #pragma unroll
                    for (int i = 0; i < 8; i++)
                        ffma2(acc[i][m], ad[i], w2);
                }
            }
        }
    }
}

// ---------- N=64 GEMM (layer 3 forward), one scalar column per thread ----------
__device__ __forceinline__ void gemm64(const float* __restrict__ W, int ldw,
                                       const float* __restrict__ sA, int lda,
                                       float* __restrict__ sWT,
                                       float (&acc)[8], int tid) {
    const int rgrp = tid >> 6;
    const int cgrp = tid & 63;
    for (int k0 = 0; k0 < 256; k0 += KT) {
        __syncthreads();
        #pragma unroll
        for (int idx = tid; idx < 64 * KT; idx += NTHREADS) {
            int kk = idx % KT;
            int n  = idx / KT;
            sWT[kk * SW + n] = W[n * ldw + k0 + kk];
        }
        __syncthreads();
        #pragma unroll 2
        for (int kq = 0; kq < KT / 4; kq++) {
            float4 av[8];
            #pragma unroll
            for (int i = 0; i < 8; i++)
                av[i] = *reinterpret_cast<const float4*>(
                            &sA[(rgrp * 8 + i) * lda + k0 + kq * 4]);
            #pragma unroll
            for (int q = 0; q < 4; q++) {
                float w = sWT[(kq * 4 + q) * SW + cgrp];
                #pragma unroll
                for (int i = 0; i < 8; i++) {
                    float a = (q == 0) ? av[i].x : (q == 1) ? av[i].y
                            : (q == 2) ? av[i].z : av[i].w;
                    acc[i] = fmaf(a, w, acc[i]);
                }
            }
        }
    }
}

__device__ __forceinline__ float redux32(float v) {
    v += __shfl_xor_sync(0xffffffffu, v, 16);
    v += __shfl_xor_sync(0xffffffffu, v, 8);
    v += __shfl_xor_sync(0xffffffffu, v, 4);
    v += __shfl_xor_sync(0xffffffffu, v, 2);
    v += __shfl_xor_sync(0xffffffffu, v, 1);
    return v;
}

__global__ void __launch_bounds__(NTHREADS, 1)
clf_kernel(const float* __restrict__ x,
           const float* __restrict__ Vw1, const float* __restrict__ Vb1,
           const float* __restrict__ Vw2, const float* __restrict__ Vb2,
           const float* __restrict__ Vw3, const float* __restrict__ Vb3,
           const float* __restrict__ Uw1, const float* __restrict__ Ub1,
           const float* __restrict__ Uw2, const float* __restrict__ Ub2,
           const float* __restrict__ Uw3, const float* __restrict__ Ub3,
           float* __restrict__ out) {
    extern __shared__ char smem_raw[];
    SmemLayout& S = *reinterpret_cast<SmemLayout*>(smem_raw);
    const int tid  = threadIdx.x;
    const int rgrp = tid >> 6;
    const int cgrp = tid & 63;
    const int wh   = (tid >> 5) & 1;   // warp half within the 64-thread rgrp
    const int lane = tid & 31;
    const int base = blockIdx.x * ROWS;

    // ---- load x tile (64 x 4) ----
    if (tid < 256) {
        int b = tid >> 2, j = tid & 3;
        S.X[b][j] = x[(base + b) * 4 + j];
    }
    __syncthreads();

    // ---- a1 = tanh(x @ Vw1^T + Vb1); thread pair (unit, half) ----
    {
        int unit = tid >> 1, h = tid & 1;
        float4 w = *reinterpret_cast<const float4*>(&Vw1[unit * 4]);
        float bb = Vb1[unit];
        #pragma unroll 4
        for (int b = h * 32; b < h * 32 + 32; b++) {
            float z = fmaf(S.X[b][0], w.x, bb);
            z = fmaf(S.X[b][1], w.y, z);
            z = fmaf(S.X[b][2], w.z, z);
            z = fmaf(S.X[b][3], w.w, z);
            S.A1[b * SA + unit] = tanhf(z);
        }
    }

    // ---- a2 = tanh(a1 @ Vw2^T + Vb2) ----
    {
        ull acc[8][2];
        #pragma unroll
        for (int i = 0; i < 8; i++) { acc[i][0] = 0ull; acc[i][1] = 0ull; }
        gemm256<256, false>(Vw2, 256, S.A1, SA, S.WT, acc, tid);
        #pragma unroll
        for (int m = 0; m < 2; m++) {
            int n0 = 2 * (cgrp + 64 * m);
            float2 bb = *reinterpret_cast<const float2*>(&Vb2[n0]);
            #pragma unroll
            for (int i = 0; i < 8; i++) {
                float lo, hi; unpack2(acc[i][m], lo, hi);
                float2 r;
                r.x = tanhf(lo + bb.x);
                r.y = tanhf(hi + bb.y);
                *reinterpret_cast<float2*>(&S.A2[(rgrp * 8 + i) * SA + n0]) = r;
            }
        }
    }

    // ---- a3 = tanh(a2 @ Vw3^T + Vb3); V = 0.5*sum a3^2; A3 = a3*(1-a3^2) ----
    {
        float acc[8];
        #pragma unroll
        for (int i = 0; i < 8; i++) acc[i] = 0.f;
        gemm64(Vw3, 256, S.A2, SA, S.WT, acc, tid);
        float bb = Vb3[cgrp];
        float pV[8];
        #pragma unroll
        for (int i = 0; i < 8; i++) {
            float a3 = tanhf(acc[i] + bb);
            pV[i] = a3 * a3;
            S.A3[(rgrp * 8 + i) * S3A + cgrp] = a3 * (1.f - a3 * a3);
        }
        #pragma unroll
        for (int i = 0; i < 8; i++) {
            float v = redux32(pV[i]);
            if (lane == 0) S.Vpart[rgrp][wh][i] = v;
        }
    }

    // ---- t2' = (w3 @ Vw3) * (1 - a2^2), written in place into A2 ----
    {
        ull acc[8][2];
        #pragma unroll
        for (int i = 0; i < 8; i++) { acc[i][0] = 0ull; acc[i][1] = 0ull; }
        gemm256<64, true>(Vw3, 256, S.A3, S3A, S.WT, acc, tid);
        #pragma unroll
        for (int m = 0; m < 2; m++) {
            int n0 = 2 * (cgrp + 64 * m);
            #pragma unroll
            for (int i = 0; i < 8; i++) {
                int off = (rgrp * 8 + i) * SA + n0;
                float2 a2v = *reinterpret_cast<const float2*>(&S.A2[off]);
                float lo, hi; unpack2(acc[i][m], lo, hi);
                float2 r;
                r.x = lo * (1.f - a2v.x * a2v.x);
                r.y = hi * (1.f - a2v.y * a2v.y);
                *reinterpret_cast<float2*>(&S.A2[off]) = r;
            }
        }
    }

    // ---- t1' = (t2' @ Vw2) * (1 - a1^2);  grad_V = t1' @ Vw1 ----
    {
        ull acc[8][2];
        #pragma unroll
        for (int i = 0; i < 8; i++) { acc[i][0] = 0ull; acc[i][1] = 0ull; }
        gemm256<256, true>(Vw2, 256, S.A2, SA, S.WT, acc, tid);
        float gp[8][4];
        #pragma unroll
        for (int i = 0; i < 8; i++)
            #pragma unroll
            for (int j = 0; j < 4; j++) gp[i][j] = 0.f;
        #pragma unroll
        for (int m = 0; m < 2; m++) {
            int n0 = 2 * (cgrp + 64 * m);
            float4 wa = *reinterpret_cast<const float4*>(&Vw1[n0 * 4]);
            float4 wb = *reinterpret_cast<const float4*>(&Vw1[(n0 + 1) * 4]);
            #pragma unroll
            for (int i = 0; i < 8; i++) {
                float2 a1v = *reinterpret_cast<const float2*>(
                                 &S.A1[(rgrp * 8 + i) * SA + n0]);
                float lo, hi; unpack2(acc[i][m], lo, hi);
                float t1lo = lo * (1.f - a1v.x * a1v.x);
                float t1hi = hi * (1.f - a1v.y * a1v.y);
                gp[i][0] = fmaf(t1lo, wa.x, fmaf(t1hi, wb.x, gp[i][0]));
                gp[i][1] = fmaf(t1lo, wa.y, fmaf(t1hi, wb.y, gp[i][1]));
                gp[i][2] = fmaf(t1lo, wa.z, fmaf(t1hi, wb.z, gp[i][2]));
                gp[i][3] = fmaf(t1lo, wa.w, fmaf(t1hi, wb.w, gp[i][3]));
            }
        }
        #pragma unroll
        for (int i = 0; i < 8; i++)
            #pragma unroll
            for (int j = 0; j < 4; j++) {
                float v = redux32(gp[i][j]);
                if (lane == 0) S.Gpart[rgrp][wh][i][j] = v;
            }
    }
    __syncthreads();  // A1/Gpart/Vpart settled

    // combine cross-warp partials
    if (tid < 64) {
        int b = tid;
        S.Vv[b] = 0.5f * (S.Vpart[b >> 3][0][b & 7] + S.Vpart[b >> 3][1][b & 7]);
    } else if (tid >= 128 && tid < 384) {
        int t = tid - 128;
        int b = t >> 2, j = t & 3;
        S.Grad[b * 4 + j] =
            S.Gpart[b >> 3][0][b & 7][j] + S.Gpart[b >> 3][1][b & 7][j];
    }

    // ---- u1 = tanh(x @ Uw1^T + Ub1), overwrite A1 ----
    {
        int unit = tid >> 1, h = tid & 1;
        float4 w = *reinterpret_cast<const float4*>(&Uw1[unit * 4]);
        float bb = Ub1[unit];
        #pragma unroll 4
        for (int b = h * 32; b < h * 32 + 32; b++) {
            float z = fmaf(S.X[b][0], w.x, bb);
            z = fmaf(S.X[b][1], w.y, z);
            z = fmaf(S.X[b][2], w.z, z);
            z = fmaf(S.X[b][3], w.w, z);
            S.A1[b * SA + unit] = tanhf(z);
        }
    }

    // ---- u2 = tanh(u1 @ Uw2^T + Ub2); fold dot with Uw3 ----
    {
        ull acc[8][2];
        #pragma unroll
        for (int i = 0; i < 8; i++) { acc[i][0] = 0ull; acc[i][1] = 0ull; }
        gemm256<256, false>(Uw2, 256, S.A1, SA, S.WT, acc, tid);
        float pu[8];
        #pragma unroll
        for (int i = 0; i < 8; i++) pu[i] = 0.f;
        #pragma unroll
        for (int m = 0; m < 2; m++) {
            int n0 = 2 * (cgrp + 64 * m);
            float2 uw = *reinterpret_cast<const float2*>(&Uw3[n0]);
            float2 bb = *reinterpret_cast<const float2*>(&Ub2[n0]);
            #pragma unroll
            for (int i = 0; i < 8; i++) {
                float lo, hi; unpack2(acc[i][m], lo, hi);
                pu[i] = fmaf(tanhf(lo + bb.x), uw.x, pu[i]);
                pu[i] = fmaf(tanhf(hi + bb.y), uw.y, pu[i]);
            }
        }
        #pragma unroll
        for (int i = 0; i < 8; i++) {
            float v = redux32(pu[i]);
            if (lane == 0) S.Upart[rgrp][wh][i] = v;
        }
    }
    __syncthreads();

    // ---- per-row epilogue: dynamics + Vdot + writes ----
    if (tid < ROWS) {
        int b = tid;
        float uu = S.Upart[b >> 3][0][b & 7] + S.Upart[b >> 3][1][b & 7];
        float u = 20.f * tanhf(uu + Ub3[0]);
        float th = S.X[b][1], v = S.X[b][2], om = S.X[b][3];
        float s, c;
        sincosf(th, &s, &c);
        float den1 = c - 24.7f;
        float den2 = c * c - 24.7f;
        float f2 = (c * (9.8f * s + 11.5f * v) + 68.4f * v - 1.2f * om * om * s) / den1;
        float f3 = (-58.8f * v * c - 243.5f * v - s * (208.3f + om * om * c)) / den2;
        float g2 = (-1.8f * c - 10.9f) / den1;
        float g3 = (9.3f * c + 38.6f) / den2;
        float gv0 = S.Grad[b * 4 + 0], gv1 = S.Grad[b * 4 + 1];
        float gv2 = S.Grad[b * 4 + 2], gv3 = S.Grad[b * 4 + 3];
        float Lf = gv0 * v + gv1 * om + gv2 * f2 + gv3 * f3;
        float Lg = gv2 * g2 + gv3 * g3;
        int row = base + b;
        out[row]           = u;            // u  [BS,1]
        out[BSZ + row]     = S.Vv[b];      // V  [BS]
        out[2 * BSZ + row] = Lf + Lg * u;  // Vdot [BS,1,1]
    }
}

extern "C" void kernel_launch(void* const* d_in, const int* in_sizes, int n_in,
                              void* d_out, int out_size) {
    const float* x   = (const float*)d_in[0];
    const float* Vw1 = (const float*)d_in[1];
    const float* Vb1 = (const float*)d_in[2];
    const float* Vw2 = (const float*)d_in[3];
    const float* Vb2 = (const float*)d_in[4];
    const float* Vw3 = (const float*)d_in[5];
    const float* Vb3 = (const float*)d_in[6];
    const float* Uw1 = (const float*)d_in[7];
    const float* Ub1 = (const float*)d_in[8];
    const float* Uw2 = (const float*)d_in[9];
    const float* Ub2 = (const float*)d_in[10];
    const float* Uw3 = (const float*)d_in[11];
    const float* Ub3 = (const float*)d_in[12];
    float* out = (float*)d_out;

    cudaFuncSetAttribute(clf_kernel, cudaFuncAttributeMaxDynamicSharedMemorySize,
                         (int)sizeof(SmemLayout));
    clf_kernel<<<BSZ / ROWS, NTHREADS, sizeof(SmemLayout)>>>(
        x, Vw1, Vb1, Vw2, Vb2, Vw3, Vb3, Uw1, Ub1, Uw2, Ub2, Uw3, Ub3, out);
}

// round 6
// speedup vs baseline: 1.0004x; 1.0003x over previous
#include <cuda_runtime.h>
#include <math.h>

#define BSZ      131072
#define ROWS     64
#define NTHREADS 512
#define KT       64
#define SA       260   // stride for 256-wide activation buffers (mult of 4)
#define S3A      68    // stride for 64-wide a3/w3 buffer (mult of 4)
#define SW       258   // stride for staged weight tile rows (even; mod 32 = 2)

struct SmemLayout {
    float X[ROWS][4];
    float A1[ROWS * SA];
    float A2[ROWS * SA];
    float A3[ROWS * S3A];
    float WT[KT * SW];
    float Vpart[8][2][8];
    float Upart[8][2][8];
    float Gpart[8][2][8][4];
    float Grad[ROWS * 4];
    float Vv[ROWS];
    float Uu[ROWS];
};

typedef unsigned long long ull;

__device__ __forceinline__ ull dup2(float a) {
    ull r; unsigned int u = __float_as_uint(a);
    asm("mov.b64 %0, {%1, %1};" : "=l"(r) : "r"(u));
    return r;
}
__device__ __forceinline__ void unpack2(ull v, float& lo, float& hi) {
    unsigned int l, h;
    asm("mov.b64 {%0, %1}, %2;" : "=r"(l), "=r"(h) : "l"(v));
    lo = __uint_as_float(l); hi = __uint_as_float(h);
}
__device__ __forceinline__ void ffma2(ull& d, ull a, ull b) {
    asm("fma.rn.f32x2 %0, %1, %2, %0;" : "+l"(d) : "l"(a), "l"(b));
}

// ---------- N=256 GEMM, packed output-column pairs ----------
// Thread (rgrp = tid>>6, cgrp = tid&63) owns rows rgrp*8..+7 and column pairs
// n0 = 2*(cgrp + 64*m), m in {0,1}.  A warp shares one rgrp -> act loads are
// warp broadcasts; weight loads are lane-consecutive LDS.64.
// TRANSW=false: W is [256][ldw], stage W[n][k]   (forward: z = a @ W^T)
// TRANSW=true : W is [K][ldw],   stage W[k][n]   (backward: t = v @ W)
template <int K, bool TRANSW>
__device__ __forceinline__ void gemm256(const float* __restrict__ W, int ldw,
                                        const float* __restrict__ sA, int lda,
                                        float* __restrict__ sWT,
                                        ull (&acc)[8][2], int tid) {
    const int rgrp = tid >> 6;
    const int cgrp = tid & 63;
    for (int k0 = 0; k0 < K; k0 += KT) {
        __syncthreads();
        if (TRANSW) {
            #pragma unroll
            for (int idx = tid; idx < 256 * KT / 2; idx += NTHREADS) {
                int n2 = idx % 128;          // float2 index within row
                int kk = idx / 128;
                *reinterpret_cast<float2*>(&sWT[kk * SW + n2 * 2]) =
                    *reinterpret_cast<const float2*>(&W[(k0 + kk) * ldw + n2 * 2]);
            }
        } else {
            #pragma unroll
            for (int idx = tid; idx < 256 * KT; idx += NTHREADS) {
                int kk = idx % KT;           // consecutive tid -> consecutive kk
                int n  = idx / KT;
                sWT[kk * SW + n] = W[n * ldw + k0 + kk];
            }
        }
        __syncthreads();
        #pragma unroll 2
        for (int kq = 0; kq < KT / 4; kq++) {
            float4 av[8];
            #pragma unroll
            for (int i = 0; i < 8; i++)
                av[i] = *reinterpret_cast<const float4*>(
                            &sA[(rgrp * 8 + i) * lda + k0 + kq * 4]);
            #pragma unroll
            for (int q = 0; q < 4; q++) {
                ull ad[8];
                #pragma unroll
                for (int i = 0; i < 8; i++) {
                    float a = (q == 0) ? av[i].x : (q == 1) ? av[i].y
                            : (q == 2) ? av[i].z : av[i].w;
                    ad[i] = dup2(a);
                }
                const float* wrow = sWT + (kq * 4 + q) * SW;
                #pragma unroll
                for (int m = 0; m < 2; m++) {
                    ull w2 = *reinterpret_cast<const ull*>(
                                 &wrow[2 * (cgrp + 64 * m)]);
                    #pragma unroll
                    for (int i = 0; i < 8; i++)
                        ffma2(acc[i][m], ad[i], w2);
                }
            }
        }
    }
}

// ---------- N=64 GEMM (layer 3 forward), one scalar column per thread ----------
__device__ __forceinline__ void gemm64(const float* __restrict__ W, int ldw,
                                       const float* __restrict__ sA, int lda,
                                       float* __restrict__ sWT,
                                       float (&acc)[8], int tid) {
    const int rgrp = tid >> 6;
    const int cgrp = tid & 63;
    for (int k0 = 0; k0 < 256; k0 += KT) {
        __syncthreads();
        #pragma unroll
        for (int idx = tid; idx < 64 * KT; idx += NTHREADS) {
            int kk = idx % KT;
            int n  = idx / KT;
            sWT[kk * SW + n] = W[n * ldw + k0 + kk];
        }
        __syncthreads();
        #pragma unroll 2
        for (int kq = 0; kq < KT / 4; kq++) {
            float4 av[8];
            #pragma unroll
            for (int i = 0; i < 8; i++)
                av[i] = *reinterpret_cast<const float4*>(
                            &sA[(rgrp * 8 + i) * lda + k0 + kq * 4]);
            #pragma unroll
            for (int q = 0; q < 4; q++) {
                float w = sWT[(kq * 4 + q) * SW + cgrp];
                #pragma unroll
                for (int i = 0; i < 8; i++) {
                    float a = (q == 0) ? av[i].x : (q == 1) ? av[i].y
                            : (q == 2) ? av[i].z : av[i].w;
                    acc[i] = fmaf(a, w, acc[i]);
                }
            }
        }
    }
}

__device__ __forceinline__ float redux32(float v) {
    v += __shfl_xor_sync(0xffffffffu, v, 16);
    v += __shfl_xor_sync(0xffffffffu, v, 8);
    v += __shfl_xor_sync(0xffffffffu, v, 4);
    v += __shfl_xor_sync(0xffffffffu, v, 2);
    v += __shfl_xor_sync(0xffffffffu, v, 1);
    return v;
}

__global__ void __launch_bounds__(NTHREADS, 1)
clf_kernel(const float* __restrict__ x,
           const float* __restrict__ Vw1, const float* __restrict__ Vb1,
           const float* __restrict__ Vw2, const float* __restrict__ Vb2,
           const float* __restrict__ Vw3, const float* __restrict__ Vb3,
           const float* __restrict__ Uw1, const float* __restrict__ Ub1,
           const float* __restrict__ Uw2, const float* __restrict__ Ub2,
           const float* __restrict__ Uw3, const float* __restrict__ Ub3,
           float* __restrict__ out) {
    extern __shared__ char smem_raw[];
    SmemLayout& S = *reinterpret_cast<SmemLayout*>(smem_raw);
    const int tid  = threadIdx.x;
    const int rgrp = tid >> 6;
    const int cgrp = tid & 63;
    const int wh   = (tid >> 5) & 1;   // warp half within the 64-thread rgrp
    const int lane = tid & 31;
    const int base = blockIdx.x * ROWS;

    // ---- load x tile (64 x 4) ----
    if (tid < 256) {
        int b = tid >> 2, j = tid & 3;
        S.X[b][j] = x[(base + b) * 4 + j];
    }
    __syncthreads();

    // ---- a1 = tanh(x @ Vw1^T + Vb1); thread pair (unit, half) ----
    {
        int unit = tid >> 1, h = tid & 1;
        float4 w = *reinterpret_cast<const float4*>(&Vw1[unit * 4]);
        float bb = Vb1[unit];
        #pragma unroll 4
        for (int b = h * 32; b < h * 32 + 32; b++) {
            float z = fmaf(S.X[b][0], w.x, bb);
            z = fmaf(S.X[b][1], w.y, z);
            z = fmaf(S.X[b][2], w.z, z);
            z = fmaf(S.X[b][3], w.w, z);
            S.A1[b * SA + unit] = tanhf(z);
        }
    }

    // ---- a2 = tanh(a1 @ Vw2^T + Vb2) ----
    {
        ull acc[8][2];
        #pragma unroll
        for (int i = 0; i < 8; i++) { acc[i][0] = 0ull; acc[i][1] = 0ull; }
        gemm256<256, false>(Vw2, 256, S.A1, SA, S.WT, acc, tid);
        #pragma unroll
        for (int m = 0; m < 2; m++) {
            int n0 = 2 * (cgrp + 64 * m);
            float2 bb = *reinterpret_cast<const float2*>(&Vb2[n0]);
            #pragma unroll
            for (int i = 0; i < 8; i++) {
                float lo, hi; unpack2(acc[i][m], lo, hi);
                float2 r;
                r.x = tanhf(lo + bb.x);
                r.y = tanhf(hi + bb.y);
                *reinterpret_cast<float2*>(&S.A2[(rgrp * 8 + i) * SA + n0]) = r;
            }
        }
    }

    // ---- a3 = tanh(a2 @ Vw3^T + Vb3); V = 0.5*sum a3^2; A3 = a3*(1-a3^2) ----
    {
        float acc[8];
        #pragma unroll
        for (int i = 0; i < 8; i++) acc[i] = 0.f;
        gemm64(Vw3, 256, S.A2, SA, S.WT, acc, tid);
        float bb = Vb3[cgrp];
        float pV[8];
        #pragma unroll
        for (int i = 0; i < 8; i++) {
            float a3 = tanhf(acc[i] + bb);
            pV[i] = a3 * a3;
            S.A3[(rgrp * 8 + i) * S3A + cgrp] = a3 * (1.f - a3 * a3);
        }
        #pragma unroll
        for (int i = 0; i < 8; i++) {
            float v = redux32(pV[i]);
            if (lane == 0) S.Vpart[rgrp][wh][i] = v;
        }
    }

    // ---- t2' = (w3 @ Vw3) * (1 - a2^2), written in place into A2 ----
    {
        ull acc[8][2];
        #pragma unroll
        for (int i = 0; i < 8; i++) { acc[i][0] = 0ull; acc[i][1] = 0ull; }
        gemm256<64, true>(Vw3, 256, S.A3, S3A, S.WT, acc, tid);
        #pragma unroll
        for (int m = 0; m < 2; m++) {
            int n0 = 2 * (cgrp + 64 * m);
            #pragma unroll
            for (int i = 0; i < 8; i++) {
                int off = (rgrp * 8 + i) * SA + n0;
                float2 a2v = *reinterpret_cast<const float2*>(&S.A2[off]);
                float lo, hi; unpack2(acc[i][m], lo, hi);
                float2 r;
                r.x = lo * (1.f - a2v.x * a2v.x);
                r.y = hi * (1.f - a2v.y * a2v.y);
                *reinterpret_cast<float2*>(&S.A2[off]) = r;
            }
        }
    }

    // ---- t1' = (t2' @ Vw2) * (1 - a1^2);  grad_V = t1' @ Vw1 ----
    {
        ull acc[8][2];
        #pragma unroll
        for (int i = 0; i < 8; i++) { acc[i][0] = 0ull; acc[i][1] = 0ull; }
        gemm256<256, true>(Vw2, 256, S.A2, SA, S.WT, acc, tid);
        float gp[8][4];
        #pragma unroll
        for (int i = 0; i < 8; i++)
            #pragma unroll
            for (int j = 0; j < 4; j++) gp[i][j] = 0.f;
        #pragma unroll
        for (int m = 0; m < 2; m++) {
            int n0 = 2 * (cgrp + 64 * m);
            float4 wa = *reinterpret_cast<const float4*>(&Vw1[n0 * 4]);
            float4 wb = *reinterpret_cast<const float4*>(&Vw1[(n0 + 1) * 4]);
            #pragma unroll
            for (int i = 0; i < 8; i++) {
                float2 a1v = *reinterpret_cast<const float2*>(
                                 &S.A1[(rgrp * 8 + i) * SA + n0]);
                float lo, hi; unpack2(acc[i][m], lo, hi);
                float t1lo = lo * (1.f - a1v.x * a1v.x);
                float t1hi = hi * (1.f - a1v.y * a1v.y);
                gp[i][0] = fmaf(t1lo, wa.x, fmaf(t1hi, wb.x, gp[i][0]));
                gp[i][1] = fmaf(t1lo, wa.y, fmaf(t1hi, wb.y, gp[i][1]));
                gp[i][2] = fmaf(t1lo, wa.z, fmaf(t1hi, wb.z, gp[i][2]));
                gp[i][3] = fmaf(t1lo, wa.w, fmaf(t1hi, wb.w, gp[i][3]));
            }
        }
        #pragma unroll
        for (int i = 0; i < 8; i++)
            #pragma unroll
            for (int j = 0; j < 4; j++) {
                float v = redux32(gp[i][j]);
                if (lane == 0) S.Gpart[rgrp][wh][i][j] = v;
            }
    }
    __syncthreads();  // A1/Gpart/Vpart settled

    // combine cross-warp partials
    if (tid < 64) {
        int b = tid;
        S.Vv[b] = 0.5f * (S.Vpart[b >> 3][0][b & 7] + S.Vpart[b >> 3][1][b & 7]);
    } else if (tid >= 128 && tid < 384) {
        int t = tid - 128;
        int b = t >> 2, j = t & 3;
        S.Grad[b * 4 + j] =
            S.Gpart[b >> 3][0][b & 7][j] + S.Gpart[b >> 3][1][b & 7][j];
    }

    // ---- u1 = tanh(x @ Uw1^T + Ub1), overwrite A1 ----
    {
        int unit = tid >> 1, h = tid & 1;
        float4 w = *reinterpret_cast<const float4*>(&Uw1[unit * 4]);
        float bb = Ub1[unit];
        #pragma unroll 4
        for (int b = h * 32; b < h * 32 + 32; b++) {
            float z = fmaf(S.X[b][0], w.x, bb);
            z = fmaf(S.X[b][1], w.y, z);
            z = fmaf(S.X[b][2], w.z, z);
            z = fmaf(S.X[b][3], w.w, z);
            S.A1[b * SA + unit] = tanhf(z);
        }
    }

    // ---- u2 = tanh(u1 @ Uw2^T + Ub2); fold dot with Uw3 ----
    {
        ull acc[8][2];
        #pragma unroll
        for (int i = 0; i < 8; i++) { acc[i][0] = 0ull; acc[i][1] = 0ull; }
        gemm256<256, false>(Uw2, 256, S.A1, SA, S.WT, acc, tid);
        float pu[8];
        #pragma unroll
        for (int i = 0; i < 8; i++) pu[i] = 0.f;
        #pragma unroll
        for (int m = 0; m < 2; m++) {
            int n0 = 2 * (cgrp + 64 * m);
            float2 uw = *reinterpret_cast<const float2*>(&Uw3[n0]);
            float2 bb = *reinterpret_cast<const float2*>(&Ub2[n0]);
            #pragma unroll
            for (int i = 0; i < 8; i++) {
                float lo, hi; unpack2(acc[i][m], lo, hi);
                pu[i] = fmaf(tanhf(lo + bb.x), uw.x, pu[i]);
                pu[i] = fmaf(tanhf(hi + bb.y), uw.y, pu[i]);
            }
        }
        #pragma unroll
        for (int i = 0; i < 8; i++) {
            float v = redux32(pu[i]);
            if (lane == 0) S.Upart[rgrp][wh][i] = v;
        }
    }
    __syncthreads();

    // ---- per-row epilogue: dynamics + Vdot + writes ----
    if (tid < ROWS) {
        int b = tid;
        float uu = S.Upart[b >> 3][0][b & 7] + S.Upart[b >> 3][1][b & 7];
        float u = 20.f * tanhf(uu + Ub3[0]);
        float th = S.X[b][1], v = S.X[b][2], om = S.X[b][3];
        float s, c;
        sincosf(th, &s, &c);
        float den1 = c - 24.7f;
        float den2 = c * c - 24.7f;
        float f2 = (c * (9.8f * s + 11.5f * v) + 68.4f * v - 1.2f * om * om * s) / den1;
        float f3 = (-58.8f * v * c - 243.5f * v - s * (208.3f + om * om * c)) / den2;
        float g2 = (-1.8f * c - 10.9f) / den1;
        float g3 = (9.3f * c + 38.6f) / den2;
        float gv0 = S.Grad[b * 4 + 0], gv1 = S.Grad[b * 4 + 1];
        float gv2 = S.Grad[b * 4 + 2], gv3 = S.Grad[b * 4 + 3];
        float Lf = gv0 * v + gv1 * om + gv2 * f2 + gv3 * f3;
        float Lg = gv2 * g2 + gv3 * g3;
        int row = base + b;
        out[row]           = u;            // u  [BS,1]
        out[BSZ + row]     = S.Vv[b];      // V  [BS]
        out[2 * BSZ + row] = Lf + Lg * u;  // Vdot [BS,1,1]
    }
}

extern "C" void kernel_launch(void* const* d_in, const int* in_sizes, int n_in,
                              void* d_out, int out_size) {
    const float* x   = (const float*)d_in[0];
    const float* Vw1 = (const float*)d_in[1];
    const float* Vb1 = (const float*)d_in[2];
    const float* Vw2 = (const float*)d_in[3];
    const float* Vb2 = (const float*)d_in[4];
    const float* Vw3 = (const float*)d_in[5];
    const float* Vb3 = (const float*)d_in[6];
    const float* Uw1 = (const float*)d_in[7];
    const float* Ub1 = (const float*)d_in[8];
    const float* Uw2 = (const float*)d_in[9];
    const float* Ub2 = (const float*)d_in[10];
    const float* Uw3 = (const float*)d_in[11];
    const float* Ub3 = (const float*)d_in[12];
    float* out = (float*)d_out;

    cudaFuncSetAttribute(clf_kernel, cudaFuncAttributeMaxDynamicSharedMemorySize,
                         (int)sizeof(SmemLayout));
    clf_kernel<<<BSZ / ROWS, NTHREADS, sizeof(SmemLayout)>>>(
        x, Vw1, Vb1, Vw2, Vb2, Vw3, Vb3, Uw1, Ub1, Uw2, Ub2, Uw3, Ub3, out);
}